// round 9
// baseline (speedup 1.0000x reference)
#include <cuda_runtime.h>
#include <cuda_pipeline.h>

// SKA forward: out[b, g*16+cg, h, w] = sum_{k} x_pad[b, g*16+cg, h+di, w+dj] * w[b, cg, k, h, w]
// x (16,512,56,56) f32, w (16,16,9,56,56) f32, out (16,512,56,56) f32.
//
// R9: cp.async pipelined smem kernel. Block = (b, cg, 8-row h-tile).
//  - w tile (9 k x 8 rows x 56) cp.async'd once into smem, then per-thread 9
//    float4 regs (amortized over all 32 groups).
//  - x planes (10 rows incl. vertical halo) stream through a 6-slot smem ring,
//    one group per pipeline stage, 5 stages in flight (register-free MLP).
//  - smem rows padded to 60 floats with permanent zeros; a guard float sits
//    before the ring. All halos (left/right/top/bottom) read structural zeros:
//    zero predicates, zero shuffles in the compute loop.
//  - 112 of 128 threads compute: thread = (row 0..7, w4 0..13), 32 groups each.

#define NB   16
#define NC   512
#define NG   32
#define NCG  16
#define NH   56
#define NW   56
#define NW4  14
#define PLANE   (NH * NW)       // 3136
#define CSTRIDE (NCG * PLANE)   // group stride in x/out
#define HT    8                 // output rows per block
#define NHT   (NH / HT)         // 7 h-tiles
#define XROW  60                // padded smem row (floats), 16B-aligned stride
#define XSLOT (10 * XROW)       // 600 floats per ring slot (10 rows)
#define NSLOT 6
#define XCHUNKS 140             // 10 rows * 14 float4 per stage
#define WCHUNKS (9 * HT * NW4)  // 1008

__global__ __launch_bounds__(128, 5) void ska_kernel(
    const float* __restrict__ x,
    const float* __restrict__ wt,
    float* __restrict__ out)
{
    __shared__ __align__(16) float xs[4 + NSLOT * XSLOT]; // [guard pad][ring]
    __shared__ __align__(16) float ws[9 * HT * NW];       // w tile

    const int tid = threadIdx.x;
    const int bid = blockIdx.x;            // (b * NCG + cg) * NHT + ht
    const int ht  = bid % NHT;
    const int cg  = (bid / NHT) % NCG;
    const int b   = bid / (NHT * NCG);
    const int h0  = ht * HT;

    const float* xplane0 = x  + (b * NC + cg) * PLANE;                 // group 0
    const float* wbase   = wt + (b * NCG + cg) * 9 * PLANE;
    float*       oplane0 = out + (b * NC + cg) * PLANE;

    // ---- zero the x ring (incl. guard + padding) once ----
    for (int i = tid; i < 4 + NSLOT * XSLOT; i += 128) xs[i] = 0.f;
    __syncthreads();

    float* xr0 = xs + 4;  // ring base, 16B aligned; xr0[-1] is the zero guard

    // ---- stage issuers ----
    auto issue_w = [&]() {
        for (int c = tid; c < WCHUNKS; c += 128) {
            const int k    = c / (HT * NW4);
            const int rem  = c % (HT * NW4);
            const int r    = rem / NW4;
            const int col4 = rem % NW4;
            __pipeline_memcpy_async(
                ws + (k * HT + r) * NW + col4 * 4,
                wbase + (k * NH + h0 + r) * NW + col4 * 4, 16);
        }
    };
    auto issue_x = [&](int g) {
        const int slot = g % NSLOT;
        const float* xp = xplane0 + g * CSTRIDE;
        float* dstbase = xr0 + slot * XSLOT;
        for (int c = tid; c < XCHUNKS; c += 128) {
            const int rr   = c / NW4;        // 0..9 (smem row)
            const int col4 = c % NW4;
            const int hr   = h0 + rr - 1;    // global row
            if (hr >= 0 && hr < NH)
                __pipeline_memcpy_async(
                    dstbase + rr * XROW + col4 * 4,
                    xp + hr * NW + col4 * 4, 16);
        }
    };

    // ---- prologue: w group + x stages 0..5 ----
    issue_w();            __pipeline_commit();
    for (int s = 0; s < NSLOT; ++s) { issue_x(s); __pipeline_commit(); }

    // w tile ready when <=6 groups pending
    __pipeline_wait_prior(6);
    __syncthreads();

    // ---- per-thread w registers (9 float4), threads 0..111 compute ----
    const int  tr   = tid / NW4;    // output row in tile 0..7
    const int  w4   = tid % NW4;
    const bool act  = (tid < 112);

    float4 wk[9];
    if (act) {
#pragma unroll
        for (int k = 0; k < 9; ++k)
            wk[k] = *reinterpret_cast<const float4*>(ws + (k * HT + tr) * NW + w4 * 4);
    }

    float* obase = oplane0 + (h0 + tr) * NW + w4 * 4;

    // ---- main loop over 32 groups ----
    for (int g = 0; g < NG; ++g) {
        if (g <= 26) __pipeline_wait_prior(5);
        else         __pipeline_wait_prior(0);
        __syncthreads();   // stage g visible to all

        if (act) {
            const float* sp = xr0 + (g % NSLOT) * XSLOT + w4 * 4;
            float4 a = make_float4(0.f, 0.f, 0.f, 0.f);
#pragma unroll
            for (int di = 0; di < 3; ++di) {
                const float* rp = sp + (tr + di) * XROW;   // smem row tr+di
                const float4 xm = *reinterpret_cast<const float4*>(rp);
                const float  xl = rp[-1];   // zero pad / guard at edges
                const float  xr = rp[4];    // zero pad at right edge

                const float4 w0 = wk[di * 3 + 0];
                const float4 w1 = wk[di * 3 + 1];
                const float4 w2 = wk[di * 3 + 2];

                a.x = fmaf(xl,   w0.x, a.x);
                a.y = fmaf(xm.x, w0.y, a.y);
                a.z = fmaf(xm.y, w0.z, a.z);
                a.w = fmaf(xm.z, w0.w, a.w);

                a.x = fmaf(xm.x, w1.x, a.x);
                a.y = fmaf(xm.y, w1.y, a.y);
                a.z = fmaf(xm.z, w1.z, a.z);
                a.w = fmaf(xm.w, w1.w, a.w);

                a.x = fmaf(xm.y, w2.x, a.x);
                a.y = fmaf(xm.z, w2.y, a.y);
                a.z = fmaf(xm.w, w2.z, a.z);
                a.w = fmaf(xr,   w2.w, a.w);
            }
            __stcs(reinterpret_cast<float4*>(obase + g * CSTRIDE), a);
        }

        __syncthreads();   // everyone done reading slot g%NSLOT before refill
        const int gn = g + NSLOT;
        if (gn < NG) { issue_x(gn); __pipeline_commit(); }
    }
}

extern "C" void kernel_launch(void* const* d_in, const int* in_sizes, int n_in,
                              void* d_out, int out_size)
{
    const float* x  = (const float*)d_in[0];
    const float* wt = (const float*)d_in[1];
    float* out      = (float*)d_out;

    const int blocks = NB * NCG * NHT; // 1792
    ska_kernel<<<blocks, 128>>>(x, wt, out);
}

// round 10
// speedup vs baseline: 1.3200x; 1.3200x over previous
#include <cuda_runtime.h>

// SKA forward: out[b, g*16+cg, h, w] = sum_{k} x_pad[b, g*16+cg, h+di, w+dj] * w[b, cg, k, h, w]
// x (16,512,56,56) f32, w (16,16,9,56,56) f32, out (16,512,56,56) f32.
// R10: R8 compute structure (GPT=8, 9 weight float4 in regs, batched loads,
// shuffle halo) + prefetch.global.L2 two group-pairs ahead. Prefetches create
// DRAM-level MLP with zero register/scoreboard cost; demand loads hit L2.

#define NB   16
#define NC   512
#define NG   32
#define NCG  16
#define NH   56
#define NW   56
#define NW4  14            // 56 / 4
#define PLANE   (NH * NW)  // 3136
#define GSPLIT  4
#define GPT     (NG / GSPLIT)   // 8 groups per thread
#define CSTRIDE (NCG * PLANE)   // stride between consecutive groups (same cg)

__device__ __forceinline__ void pf_l2(const float* p) {
    asm volatile("prefetch.global.L2 [%0];" :: "l"(p));
}

__global__ __launch_bounds__(128, 6) void ska_kernel(
    const float* __restrict__ x,
    const float* __restrict__ wt,
    float* __restrict__ out)
{
    const int idx = blockIdx.x * 128 + threadIdx.x;
    const int lane = threadIdx.x & 31;
    // idx = (((b*GSPLIT + gs)*NCG + cg)*NH + h)*NW4 + w4
    const int w4 = idx % NW4;
    int t        = idx / NW4;
    const int h  = t % NH;  t /= NH;
    const int cg = t % NCG; t /= NCG;
    const int gs = t % GSPLIT;
    const int b  = t / GSPLIT;
    const int col = w4 * 4;

    const bool hm = (h > 0);
    const bool hp = (h < NH - 1);
    const bool wl = (col > 0);
    const bool wr = (col < NW - 4);

    const float* wb = wt + ((((b * NCG + cg) * 9) * NH + h) * NW + col);
    const int base  = (b * NC + (gs * GPT) * NCG + cg) * PLANE + h * NW + col;
    const float* xb = x + base;
    float* ob       = out + base;

    // ---- upfront: prefetch pair 1 (groups 2,3) while w-loads are in flight ----
#pragma unroll
    for (int j = 2; j < 4; ++j)
#pragma unroll
        for (int di = 0; di < 3; ++di) {
            const bool v = (di == 1) || (di == 0 && hm) || (di == 2 && hp);
            if (v) pf_l2(xb + j * CSTRIDE + (di - 1) * NW);
        }

    // ---- 9 weight float4s (reused across 8 groups) ----
    float4 wk[9];
#pragma unroll
    for (int k = 0; k < 9; ++k)
        wk[k] = *reinterpret_cast<const float4*>(wb + k * PLANE);

    // ---- main loop: pairs of groups, prefetch 2 pairs ahead ----
#pragma unroll
    for (int j = 0; j < GPT; j += 2) {
        // prefetch groups j+4, j+5
        if (j + 4 < GPT) {
#pragma unroll
            for (int jj = 0; jj < 2; ++jj)
#pragma unroll
                for (int di = 0; di < 3; ++di) {
                    const bool v = (di == 1) || (di == 0 && hm) || (di == 2 && hp);
                    if (v) pf_l2(xb + (j + 4 + jj) * CSTRIDE + (di - 1) * NW);
                }
        }

        // ---- phase 1: batch 6 independent x loads (2 groups x 3 rows) ----
        float4 xm[2][3];
#pragma unroll
        for (int jj = 0; jj < 2; ++jj)
#pragma unroll
            for (int di = 0; di < 3; ++di) {
                const bool v = (di == 1) || (di == 0 && hm) || (di == 2 && hp);
                xm[jj][di] = make_float4(0.f, 0.f, 0.f, 0.f);
                if (v) xm[jj][di] = *reinterpret_cast<const float4*>(
                                        xb + (j + jj) * CSTRIDE + (di - 1) * NW);
            }

        // ---- phase 2: shuffles + edge fixup ----
        float xl[2][3], xr[2][3];
#pragma unroll
        for (int jj = 0; jj < 2; ++jj)
#pragma unroll
            for (int di = 0; di < 3; ++di) {
                xl[jj][di] = __shfl_up_sync(0xffffffffu,  xm[jj][di].w, 1);
                xr[jj][di] = __shfl_down_sync(0xffffffffu, xm[jj][di].x, 1);
            }
#pragma unroll
        for (int jj = 0; jj < 2; ++jj)
#pragma unroll
            for (int di = 0; di < 3; ++di) {
                const bool v = (di == 1) || (di == 0 && hm) || (di == 2 && hp);
                if (lane == 0  && wl) xl[jj][di] = v ? xb[(j + jj) * CSTRIDE + (di - 1) * NW - 1] : 0.f;
                if (lane == 31 && wr) xr[jj][di] = v ? xb[(j + jj) * CSTRIDE + (di - 1) * NW + 4] : 0.f;
                if (!wl) xl[jj][di] = 0.f;
                if (!wr) xr[jj][di] = 0.f;
            }

        // ---- phase 3: FMAs + stores ----
#pragma unroll
        for (int jj = 0; jj < 2; ++jj) {
            float4 a = make_float4(0.f, 0.f, 0.f, 0.f);
#pragma unroll
            for (int di = 0; di < 3; ++di) {
                const float4 w0 = wk[di * 3 + 0];
                const float4 w1 = wk[di * 3 + 1];
                const float4 w2 = wk[di * 3 + 2];
                const float4 m  = xm[jj][di];

                a.x = fmaf(xl[jj][di], w0.x, a.x);
                a.y = fmaf(m.x,        w0.y, a.y);
                a.z = fmaf(m.y,        w0.z, a.z);
                a.w = fmaf(m.z,        w0.w, a.w);

                a.x = fmaf(m.x,        w1.x, a.x);
                a.y = fmaf(m.y,        w1.y, a.y);
                a.z = fmaf(m.z,        w1.z, a.z);
                a.w = fmaf(m.w,        w1.w, a.w);

                a.x = fmaf(m.y,        w2.x, a.x);
                a.y = fmaf(m.z,        w2.y, a.y);
                a.z = fmaf(m.w,        w2.z, a.z);
                a.w = fmaf(xr[jj][di], w2.w, a.w);
            }
            __stcs(reinterpret_cast<float4*>(ob + (j + jj) * CSTRIDE), a);
        }
    }
}

extern "C" void kernel_launch(void* const* d_in, const int* in_sizes, int n_in,
                              void* d_out, int out_size)
{
    const float* x  = (const float*)d_in[0];
    const float* wt = (const float*)d_in[1];
    float* out      = (float*)d_out;

    const int total  = NB * GSPLIT * NCG * NH * NW4; // 802816 threads
    const int blocks = total / 128;                  // 6272
    ska_kernel<<<blocks, 128>>>(x, wt, out);
}